// round 14
// baseline (speedup 1.0000x reference)
#include <cuda_runtime.h>
#include <math.h>

#define D 64
#define EPS_M 1e-7f
#define N_MAX 100001
#define NB 4            // nodes per warp-chunk (register-tiled GEMM)

__device__ float g_WT[D * D];       // g_WT[d*64 + c] = W[c][d]
__device__ int   g_off[N_MAX + 1];  // CSR offsets into sorted dst

// ---- pre-kernel: scatter-based CSR offsets + W transpose ----
// thread e writes g_off[n] = e+1 for all n in (dst[e], dst[e+1]];
// thread 0 also writes g_off[0..dst[0]] = 0. No dependent load chains.
__global__ void prep_kernel(const int* __restrict__ dst,
                            const float* __restrict__ W,
                            int n_nodes, int n_edges)
{
    const int i = blockIdx.x * blockDim.x + threadIdx.x;
    if (i < D * D) {
        int r = i >> 6, c = i & 63;       // W[r][c]
        g_WT[c * D + r] = W[i];
    }
    if (i < n_edges) {
        const int d0 = __ldg(&dst[i]);
        const int d1 = (i + 1 < n_edges) ? __ldg(&dst[i + 1]) : n_nodes;
        for (int n = d0 + 1; n <= d1; ++n) g_off[n] = i + 1;
        if (i == 0)
            for (int n = 0; n <= d0; ++n) g_off[n] = 0;
    }
}

__device__ __forceinline__ void edge_step(const float4 a, const float4 b,
                                          float4& se, float4& sme)
{
    const float m0 = fmaxf(a.x + b.x, 0.f) + EPS_M;
    const float m1 = fmaxf(a.y + b.y, 0.f) + EPS_M;
    const float m2 = fmaxf(a.z + b.z, 0.f) + EPS_M;
    const float m3 = fmaxf(a.w + b.w, 0.f) + EPS_M;
    const float p0 = __expf(m0), p1 = __expf(m1);
    const float p2 = __expf(m2), p3 = __expf(m3);
    se.x += p0; se.y += p1; se.z += p2; se.w += p3;
    sme.x = fmaf(m0, p0, sme.x); sme.y = fmaf(m1, p1, sme.y);
    sme.z = fmaf(m2, p2, sme.z); sme.w = fmaf(m3, p3, sme.w);
}

// ---- main kernel: warp handles NB consecutive nodes, then 4x64 mini-GEMM ----
// (byte-identical source to the kernel that measured 102-103us)
__global__ void __launch_bounds__(256) genconv_kernel(
    const float* __restrict__ nf,     // [N, 64]
    const float* __restrict__ ef,     // [E, 64]
    const float* __restrict__ bvec,   // [64]
    const float* __restrict__ scale,  // [1]
    const int*   __restrict__ src,    // [E]
    float*       __restrict__ out,    // [N, 64]
    int n_nodes)
{
    __shared__ float sWT[D * D];          // 16 KB
    __shared__ float s_feat[8][NB][D];    // 8 KB

    const int lane = threadIdx.x & 31;
    const int wim  = threadIdx.x >> 5;
    const int q    = lane & 15;           // channel-quad index (0..15)
    const int eo   = lane >> 4;           // edge offset (0/1): half-warp per edge
    const int c4   = q * 4;               // channels c4..c4+3 in edge loop
    const int c2   = lane * 2;            // channels c2,c2+1 in GEMM
    const int gw   = (blockIdx.x * blockDim.x + threadIdx.x) >> 5;
    const int nwarps = (gridDim.x * blockDim.x) >> 5;

    {   // stage WT once per block
        const float4* s4 = (const float4*)g_WT;
        float4* d4 = (float4*)sWT;
        for (int i = threadIdx.x; i < (D * D) / 4; i += 256) d4[i] = s4[i];
    }
    __syncthreads();

    const float sc = scale[0];
    const float2 bv = *(const float2*)(bvec + c2);
    const int nchunks = (n_nodes + NB - 1) / NB;

    for (int chunk = gw; chunk < nchunks; chunk += nwarps) {
        const int base = chunk * NB;

        #pragma unroll
        for (int i = 0; i < NB; ++i) {
            const int node = base + i;
            float4 se  = make_float4(0.f, 0.f, 0.f, 0.f);
            float4 sme = make_float4(0.f, 0.f, 0.f, 0.f);
            float4 h4  = make_float4(0.f, 0.f, 0.f, 0.f);

            if (node < n_nodes) {
                h4 = *(const float4*)(nf + node * D + c4);
                const int s    = g_off[node];
                const int eend = g_off[node + 1];
                int e = s + eo;
                // pipelined: 2 edges per half-warp per iter = 4 edges/warp in flight
                for (; e + 2 < eend; e += 4) {
                    const int sp0 = __ldg(&src[e]);
                    const int sp1 = __ldg(&src[e + 2]);
                    const float4 b0 = __ldcs((const float4*)(ef + (size_t)e * D + c4));
                    const float4 b1 = __ldcs((const float4*)(ef + (size_t)(e + 2) * D + c4));
                    const float4 a0 = *(const float4*)(nf + sp0 * D + c4);
                    const float4 a1 = *(const float4*)(nf + sp1 * D + c4);
                    edge_step(a0, b0, se, sme);
                    edge_step(a1, b1, se, sme);
                }
                if (e < eend) {
                    const int sp0 = __ldg(&src[e]);
                    const float4 b0 = __ldcs((const float4*)(ef + (size_t)e * D + c4));
                    const float4 a0 = *(const float4*)(nf + sp0 * D + c4);
                    edge_step(a0, b0, se, sme);
                }
            }
            // combine the two edge-halves (lane q <-> lane q+16)
            se.x += __shfl_xor_sync(0xffffffffu, se.x, 16);
            se.y += __shfl_xor_sync(0xffffffffu, se.y, 16);
            se.z += __shfl_xor_sync(0xffffffffu, se.z, 16);
            se.w += __shfl_xor_sync(0xffffffffu, se.w, 16);
            sme.x += __shfl_xor_sync(0xffffffffu, sme.x, 16);
            sme.y += __shfl_xor_sync(0xffffffffu, sme.y, 16);
            sme.z += __shfl_xor_sync(0xffffffffu, sme.z, 16);
            sme.w += __shfl_xor_sync(0xffffffffu, sme.w, 16);

            float4 agg;
            agg.x = (se.x > 0.f) ? (sme.x / se.x) : 0.f;
            agg.y = (se.y > 0.f) ? (sme.y / se.y) : 0.f;
            agg.z = (se.z > 0.f) ? (sme.z / se.z) : 0.f;
            agg.w = (se.w > 0.f) ? (sme.w / se.w) : 0.f;

            float a2s = fmaf(agg.x, agg.x, fmaf(agg.y, agg.y, fmaf(agg.z, agg.z, agg.w * agg.w)));
            float h2s = fmaf(h4.x, h4.x, fmaf(h4.y, h4.y, fmaf(h4.z, h4.z, h4.w * h4.w)));
            #pragma unroll
            for (int o = 8; o > 0; o >>= 1) {
                a2s += __shfl_xor_sync(0xffffffffu, a2s, o);
                h2s += __shfl_xor_sync(0xffffffffu, h2s, o);
            }

            const float coef = (sqrtf(h2s) * sc) / fmaxf(sqrtf(a2s), 1e-12f);
            if (lane < 16) {
                float4 f;
                f.x = fmaf(agg.x, coef, h4.x);
                f.y = fmaf(agg.y, coef, h4.y);
                f.z = fmaf(agg.z, coef, h4.z);
                f.w = fmaf(agg.w, coef, h4.w);
                *(float4*)&s_feat[wim][i][c4] = f;
            }
        }
        __syncwarp();

        // mini-GEMM: out[base..base+3][c2,c2+1] = b + feat @ WT
        float2 acc[NB];
        #pragma unroll
        for (int i = 0; i < NB; ++i) acc[i] = bv;

        #pragma unroll
        for (int d4 = 0; d4 < D; d4 += 4) {
            const float2 w0 = *(const float2*)(sWT + (d4 + 0) * D + c2);
            const float2 w1 = *(const float2*)(sWT + (d4 + 1) * D + c2);
            const float2 w2 = *(const float2*)(sWT + (d4 + 2) * D + c2);
            const float2 w3 = *(const float2*)(sWT + (d4 + 3) * D + c2);
            #pragma unroll
            for (int i = 0; i < NB; ++i) {
                const float4 f = *(const float4*)&s_feat[wim][i][d4];  // broadcast
                acc[i].x = fmaf(f.x, w0.x, acc[i].x); acc[i].y = fmaf(f.x, w0.y, acc[i].y);
                acc[i].x = fmaf(f.y, w1.x, acc[i].x); acc[i].y = fmaf(f.y, w1.y, acc[i].y);
                acc[i].x = fmaf(f.z, w2.x, acc[i].x); acc[i].y = fmaf(f.z, w2.y, acc[i].y);
                acc[i].x = fmaf(f.w, w3.x, acc[i].x); acc[i].y = fmaf(f.w, w3.y, acc[i].y);
            }
        }
        #pragma unroll
        for (int i = 0; i < NB; ++i)
            if (base + i < n_nodes)
                *(float2*)(out + (size_t)(base + i) * D + c2) = acc[i];
        __syncwarp();   // protect s_feat WAR for next chunk
    }
}

extern "C" void kernel_launch(void* const* d_in, const int* in_sizes, int n_in,
                              void* d_out, int out_size)
{
    const float* nf    = (const float*)d_in[0];
    const float* ef    = (const float*)d_in[1];
    const float* W     = (const float*)d_in[2];
    const float* bvec  = (const float*)d_in[3];
    const float* scale = (const float*)d_in[4];
    const int*   src   = (const int*)d_in[5];
    const int*   dst   = (const int*)d_in[6];
    float* out = (float*)d_out;

    const int n_nodes = in_sizes[0] / D;
    const int n_edges = in_sizes[5];

    // one chunk (NB nodes) per warp: nwarps == nchunks -> no quantization tail
    const int nchunks = (n_nodes + NB - 1) / NB;
    const int nblocks = (nchunks + 7) / 8;      // 8 warps per block

    prep_kernel<<<(n_edges + 255) / 256, 256>>>(dst, W, n_nodes, n_edges);
    genconv_kernel<<<nblocks, 256>>>(nf, ef, bvec, scale, src, out, n_nodes);
}

// round 15
// speedup vs baseline: 1.5585x; 1.5585x over previous
#include <cuda_runtime.h>
#include <math.h>

#define D 64
#define EPS_M 1e-7f
#define N_MAX 100001
#define NB 4            // nodes per warp-chunk (register-tiled GEMM)

__device__ float g_WT[D * D];       // g_WT[d*64 + c] = W[c][d]
__device__ int   g_off[N_MAX + 1];  // CSR offsets into sorted dst
__device__ int   g_counter;         // dynamic chunk counter (reset in prep)

// ---- pre-kernel: scatter-based CSR offsets + W transpose + counter reset ----
__global__ void prep_kernel(const int* __restrict__ dst,
                            const float* __restrict__ W,
                            int n_nodes, int n_edges)
{
    const int i = blockIdx.x * blockDim.x + threadIdx.x;
    if (i == 0) g_counter = 0;
    if (i < D * D) {
        int r = i >> 6, c = i & 63;       // W[r][c]
        g_WT[c * D + r] = W[i];
    }
    if (i < n_edges) {
        const int d0 = __ldg(&dst[i]);
        const int d1 = (i + 1 < n_edges) ? __ldg(&dst[i + 1]) : n_nodes;
        for (int n = d0 + 1; n <= d1; ++n) g_off[n] = i + 1;
        if (i == 0)
            for (int n = 0; n <= d0; ++n) g_off[n] = 0;
    }
}

__device__ __forceinline__ void edge_step(const float4 a, const float4 b,
                                          float4& se, float4& sme)
{
    const float m0 = fmaxf(a.x + b.x, 0.f) + EPS_M;
    const float m1 = fmaxf(a.y + b.y, 0.f) + EPS_M;
    const float m2 = fmaxf(a.z + b.z, 0.f) + EPS_M;
    const float m3 = fmaxf(a.w + b.w, 0.f) + EPS_M;
    const float p0 = __expf(m0), p1 = __expf(m1);
    const float p2 = __expf(m2), p3 = __expf(m3);
    se.x += p0; se.y += p1; se.z += p2; se.w += p3;
    sme.x = fmaf(m0, p0, sme.x); sme.y = fmaf(m1, p1, sme.y);
    sme.z = fmaf(m2, p2, sme.z); sme.w = fmaf(m3, p3, sme.w);
}

// ---- main kernel: warp steals NB-node chunks dynamically, then 4x64 mini-GEMM ----
// (body byte-identical to the 103us R13 kernel; only the chunk loop header changed)
__global__ void __launch_bounds__(256) genconv_kernel(
    const float* __restrict__ nf,     // [N, 64]
    const float* __restrict__ ef,     // [E, 64]
    const float* __restrict__ bvec,   // [64]
    const float* __restrict__ scale,  // [1]
    const int*   __restrict__ src,    // [E]
    float*       __restrict__ out,    // [N, 64]
    int n_nodes)
{
    __shared__ float sWT[D * D];          // 16 KB
    __shared__ float s_feat[8][NB][D];    // 8 KB

    const int lane = threadIdx.x & 31;
    const int wim  = threadIdx.x >> 5;
    const int q    = lane & 15;           // channel-quad index (0..15)
    const int eo   = lane >> 4;           // edge offset (0/1): half-warp per edge
    const int c4   = q * 4;               // channels c4..c4+3 in edge loop
    const int c2   = lane * 2;            // channels c2,c2+1 in GEMM

    {   // stage WT once per block
        const float4* s4 = (const float4*)g_WT;
        float4* d4 = (float4*)sWT;
        for (int i = threadIdx.x; i < (D * D) / 4; i += 256) d4[i] = s4[i];
    }
    __syncthreads();

    const float sc = scale[0];
    const float2 bv = *(const float2*)(bvec + c2);
    const int nchunks = (n_nodes + NB - 1) / NB;

    for (;;) {
        // dynamic work stealing: one atomic fetch per warp per chunk
        int chunk;
        if (lane == 0) chunk = atomicAdd(&g_counter, 1);
        chunk = __shfl_sync(0xffffffffu, chunk, 0);
        if (chunk >= nchunks) break;
        const int base = chunk * NB;

        #pragma unroll
        for (int i = 0; i < NB; ++i) {
            const int node = base + i;
            float4 se  = make_float4(0.f, 0.f, 0.f, 0.f);
            float4 sme = make_float4(0.f, 0.f, 0.f, 0.f);
            float4 h4  = make_float4(0.f, 0.f, 0.f, 0.f);

            if (node < n_nodes) {
                h4 = *(const float4*)(nf + node * D + c4);
                const int s    = g_off[node];
                const int eend = g_off[node + 1];
                int e = s + eo;
                // pipelined: 2 edges per half-warp per iter = 4 edges/warp in flight
                for (; e + 2 < eend; e += 4) {
                    const int sp0 = __ldg(&src[e]);
                    const int sp1 = __ldg(&src[e + 2]);
                    const float4 b0 = __ldcs((const float4*)(ef + (size_t)e * D + c4));
                    const float4 b1 = __ldcs((const float4*)(ef + (size_t)(e + 2) * D + c4));
                    const float4 a0 = *(const float4*)(nf + sp0 * D + c4);
                    const float4 a1 = *(const float4*)(nf + sp1 * D + c4);
                    edge_step(a0, b0, se, sme);
                    edge_step(a1, b1, se, sme);
                }
                if (e < eend) {
                    const int sp0 = __ldg(&src[e]);
                    const float4 b0 = __ldcs((const float4*)(ef + (size_t)e * D + c4));
                    const float4 a0 = *(const float4*)(nf + sp0 * D + c4);
                    edge_step(a0, b0, se, sme);
                }
            }
            // combine the two edge-halves (lane q <-> lane q+16)
            se.x += __shfl_xor_sync(0xffffffffu, se.x, 16);
            se.y += __shfl_xor_sync(0xffffffffu, se.y, 16);
            se.z += __shfl_xor_sync(0xffffffffu, se.z, 16);
            se.w += __shfl_xor_sync(0xffffffffu, se.w, 16);
            sme.x += __shfl_xor_sync(0xffffffffu, sme.x, 16);
            sme.y += __shfl_xor_sync(0xffffffffu, sme.y, 16);
            sme.z += __shfl_xor_sync(0xffffffffu, sme.z, 16);
            sme.w += __shfl_xor_sync(0xffffffffu, sme.w, 16);

            float4 agg;
            agg.x = (se.x > 0.f) ? (sme.x / se.x) : 0.f;
            agg.y = (se.y > 0.f) ? (sme.y / se.y) : 0.f;
            agg.z = (se.z > 0.f) ? (sme.z / se.z) : 0.f;
            agg.w = (se.w > 0.f) ? (sme.w / se.w) : 0.f;

            float a2s = fmaf(agg.x, agg.x, fmaf(agg.y, agg.y, fmaf(agg.z, agg.z, agg.w * agg.w)));
            float h2s = fmaf(h4.x, h4.x, fmaf(h4.y, h4.y, fmaf(h4.z, h4.z, h4.w * h4.w)));
            #pragma unroll
            for (int o = 8; o > 0; o >>= 1) {
                a2s += __shfl_xor_sync(0xffffffffu, a2s, o);
                h2s += __shfl_xor_sync(0xffffffffu, h2s, o);
            }

            const float coef = (sqrtf(h2s) * sc) / fmaxf(sqrtf(a2s), 1e-12f);
            if (lane < 16) {
                float4 f;
                f.x = fmaf(agg.x, coef, h4.x);
                f.y = fmaf(agg.y, coef, h4.y);
                f.z = fmaf(agg.z, coef, h4.z);
                f.w = fmaf(agg.w, coef, h4.w);
                *(float4*)&s_feat[wim][i][c4] = f;
            }
        }
        __syncwarp();

        // mini-GEMM: out[base..base+3][c2,c2+1] = b + feat @ WT
        float2 acc[NB];
        #pragma unroll
        for (int i = 0; i < NB; ++i) acc[i] = bv;

        #pragma unroll
        for (int d4 = 0; d4 < D; d4 += 4) {
            const float2 w0 = *(const float2*)(sWT + (d4 + 0) * D + c2);
            const float2 w1 = *(const float2*)(sWT + (d4 + 1) * D + c2);
            const float2 w2 = *(const float2*)(sWT + (d4 + 2) * D + c2);
            const float2 w3 = *(const float2*)(sWT + (d4 + 3) * D + c2);
            #pragma unroll
            for (int i = 0; i < NB; ++i) {
                const float4 f = *(const float4*)&s_feat[wim][i][d4];  // broadcast
                acc[i].x = fmaf(f.x, w0.x, acc[i].x); acc[i].y = fmaf(f.x, w0.y, acc[i].y);
                acc[i].x = fmaf(f.y, w1.x, acc[i].x); acc[i].y = fmaf(f.y, w1.y, acc[i].y);
                acc[i].x = fmaf(f.z, w2.x, acc[i].x); acc[i].y = fmaf(f.z, w2.y, acc[i].y);
                acc[i].x = fmaf(f.w, w3.x, acc[i].x); acc[i].y = fmaf(f.w, w3.y, acc[i].y);
            }
        }
        #pragma unroll
        for (int i = 0; i < NB; ++i)
            if (base + i < n_nodes)
                *(float2*)(out + (size_t)(base + i) * D + c2) = acc[i];
        __syncwarp();   // protect s_feat WAR for next chunk
    }
}

extern "C" void kernel_launch(void* const* d_in, const int* in_sizes, int n_in,
                              void* d_out, int out_size)
{
    const float* nf    = (const float*)d_in[0];
    const float* ef    = (const float*)d_in[1];
    const float* W     = (const float*)d_in[2];
    const float* bvec  = (const float*)d_in[3];
    const float* scale = (const float*)d_in[4];
    const int*   src   = (const int*)d_in[5];
    const int*   dst   = (const int*)d_in[6];
    float* out = (float*)d_out;

    const int n_nodes = in_sizes[0] / D;
    const int n_edges = in_sizes[5];

    prep_kernel<<<(n_edges + 255) / 256, 256>>>(dst, W, n_nodes, n_edges);
    genconv_kernel<<<1480, 256>>>(nf, ef, bvec, scale, src, out, n_nodes);
}